// round 2
// baseline (speedup 1.0000x reference)
#include <cuda_runtime.h>
#include <math.h>

#define NN 100000
#define EE 3200000
#define DD 64

// ---------------- device scratch (static, allowed) ----------------
__device__ float  d_h1[NN * DD];            // x @ W1 (shared by all 3 graphs)
__device__ float  d_h2[NN * DD];            // layer-2 gemm output
__device__ float  d_XM[(size_t)NN * 384];   // [N, 6*64] concat, row-major
__device__ int    d_csr_row[EE];
__device__ float  d_csr_w[EE];              // ew_sorted, overwritten in-place by norm
__device__ int    d_off[NN + 1];
__device__ int    d_cursor[NN];
__device__ int    d_cnt[NN];
__device__ float  d_dinv[NN];
__device__ double d_chsum[6];
__device__ float  d_catt[8];                // [0..5]=conv_w*att, [6]=conv_b

// ---------------- small utility kernels ----------------
__global__ void zero_cnt_kernel() {
    int i = blockIdx.x * blockDim.x + threadIdx.x;
    if (i < NN) d_cnt[i] = 0;
}

__global__ void zero_chsum_kernel() {
    if (threadIdx.x < 6) d_chsum[threadIdx.x] = 0.0;
}

// ---------------- CSR build ----------------
__global__ void count_kernel(const int* __restrict__ col) {
    int e = blockIdx.x * blockDim.x + threadIdx.x;
    if (e < EE) atomicAdd(&d_cnt[col[e]], 1);
}

// single-block exclusive scan of d_cnt[0..NN) -> d_off, d_cursor; d_off[NN]=E
__global__ void scan_kernel() {
    __shared__ int s[1024];
    int t = threadIdx.x;
    const int C = (NN + 1023) / 1024;   // 98
    int beg = t * C;
    int end = beg + C; if (end > NN) end = NN;
    int sum = 0;
    for (int i = beg; i < end; i++) sum += d_cnt[i];
    s[t] = sum;
    __syncthreads();
    // Hillis-Steele inclusive scan over 1024 partials
    for (int st = 1; st < 1024; st <<= 1) {
        int v = (t >= st) ? s[t - st] : 0;
        __syncthreads();
        s[t] += v;
        __syncthreads();
    }
    int run = (t == 0) ? 0 : s[t - 1];
    for (int i = beg; i < end; i++) {
        d_off[i] = run;
        d_cursor[i] = run;
        run += d_cnt[i];
    }
    if (t == 1023) d_off[NN] = s[1023];
}

__global__ void scatter_kernel(const int* __restrict__ row,
                               const int* __restrict__ col,
                               const float* __restrict__ ew) {
    int e = blockIdx.x * blockDim.x + threadIdx.x;
    if (e < EE) {
        int c = col[e];
        int p = atomicAdd(&d_cursor[c], 1);
        d_csr_row[p] = row[e];
        d_csr_w[p]   = ew[e];
    }
}

// warp per node: deg = 1 + sum(ew over incoming slice); dinv = rsqrt(deg)
__global__ void dinv_kernel() {
    int v = (blockIdx.x * blockDim.x + threadIdx.x) >> 5;
    int lane = threadIdx.x & 31;
    if (v >= NN) return;
    int b = d_off[v], e = d_off[v + 1];
    float s = 0.f;
    for (int p = b + lane; p < e; p += 32) s += d_csr_w[p];
    #pragma unroll
    for (int o = 16; o; o >>= 1) s += __shfl_xor_sync(0xffffffffu, s, o);
    if (lane == 0) d_dinv[v] = rsqrtf(1.0f + s);
}

// warp per node: ew -> norm = dinv[row]*ew*dinv[v]  (in place)
__global__ void norm_kernel() {
    int v = (blockIdx.x * blockDim.x + threadIdx.x) >> 5;
    int lane = threadIdx.x & 31;
    if (v >= NN) return;
    float dv = d_dinv[v];
    int b = d_off[v], e = d_off[v + 1];
    for (int p = b + lane; p < e; p += 32)
        d_csr_w[p] = d_dinv[d_csr_row[p]] * d_csr_w[p] * dv;
}

// ---------------- dense 64x64 GEMM over 100k rows ----------------
// out[r][d] = sum_k in[r*istride+k] * W[k*64+d]    (no bias here)
// in_ext == nullptr -> read from d_XM + xoff (stride istride)
// out_sel: 0 -> d_h1, 1 -> d_h2
__global__ void gemm_kernel(const float* __restrict__ in_ext, int istride, int xoff,
                            const float* __restrict__ W, int out_sel) {
    __shared__ float sW[64 * 64];
    __shared__ float sI[32 * 64];
    const float* in = in_ext ? in_ext : (d_XM + xoff);
    float* out = out_sel ? d_h2 : d_h1;
    int tid = threadIdx.x;
    for (int i = tid; i < 4096; i += 256) sW[i] = W[i];
    int row0 = blockIdx.x * 32;
    for (int i = tid; i < 2048; i += 256) {
        int r = i >> 6, k = i & 63;
        int rr = row0 + r;
        sI[i] = (rr < NN) ? in[(size_t)rr * istride + k] : 0.f;
    }
    __syncthreads();
    int dcol = tid & 63, rs = tid >> 6;
    for (int r = rs; r < 32; r += 4) {
        float acc = 0.f;
        #pragma unroll
        for (int k = 0; k < 64; k++) acc = fmaf(sI[r * 64 + k], sW[k * 64 + dcol], acc);
        int rr = row0 + r;
        if (rr < NN) out[(size_t)rr * 64 + dcol] = acc;
    }
}

// ---------------- aggregation: warp per node, float2 per lane ----------------
// out_v = relu( sum_p norm[p]*h[row[p]] + dinv[v]^2*h[v] + bias )
// written into d_XM at column block blk (64 floats = 32 float2)
__global__ void agg_kernel(int h_sel, const float* __restrict__ bias, int blk) {
    int v = (blockIdx.x * blockDim.x + threadIdx.x) >> 5;
    int lane = threadIdx.x & 31;
    if (v >= NN) return;
    const float2* h2 = (const float2*)(h_sel ? d_h2 : d_h1);
    float2 acc = make_float2(0.f, 0.f);
    int b = d_off[v], e = d_off[v + 1];
    for (int p = b; p < e; p++) {
        int r = __ldg(&d_csr_row[p]);
        float w = __ldg(&d_csr_w[p]);
        float2 hv = h2[(size_t)r * 32 + lane];
        acc.x = fmaf(w, hv.x, acc.x);
        acc.y = fmaf(w, hv.y, acc.y);
    }
    float dv = d_dinv[v];
    float dv2 = dv * dv;
    float2 hs = h2[(size_t)v * 32 + lane];
    acc.x = fmaf(dv2, hs.x, acc.x);
    acc.y = fmaf(dv2, hs.y, acc.y);
    float2 bb = ((const float2*)bias)[lane];
    acc.x = fmaxf(acc.x + bb.x, 0.f);
    acc.y = fmaxf(acc.y + bb.y, 0.f);
    ((float2*)d_XM)[(size_t)v * 192 + blk * 32 + lane] = acc;
}

// ---------------- channel sums for SE attention ----------------
// att_in[c] = mean of XM_flat[c*6400000 .. (c+1)*6400000)
__global__ void chsum_kernel() {
    int ch = blockIdx.x >> 7;       // 128 blocks per channel
    int bl = blockIdx.x & 127;
    size_t base = (size_t)ch * 6400000;
    float s = 0.f;
    for (size_t i = (size_t)bl * 256 + threadIdx.x; i < 6400000; i += 128 * 256)
        s += d_XM[base + i];
    #pragma unroll
    for (int o = 16; o; o >>= 1) s += __shfl_xor_sync(0xffffffffu, s, o);
    __shared__ float ws[8];
    int lane = threadIdx.x & 31, w = threadIdx.x >> 5;
    if (lane == 0) ws[w] = s;
    __syncthreads();
    if (threadIdx.x < 8) {
        float t = ws[threadIdx.x];
        #pragma unroll
        for (int o = 4; o; o >>= 1) t += __shfl_xor_sync(0xffu, t, o, 8);
        if (threadIdx.x == 0) atomicAdd(&d_chsum[ch], (double)t);
    }
}

// ---------------- tiny SE MLP: fc1(relu) -> fc2(sigmoid) -> * conv_w ----------------
__global__ void att_kernel(const float* __restrict__ fc1w, const float* __restrict__ fc1b,
                           const float* __restrict__ fc2w, const float* __restrict__ fc2b,
                           const float* __restrict__ convw, const float* __restrict__ convb) {
    if (threadIdx.x != 0 || blockIdx.x != 0) return;
    float a[6];
    for (int c = 0; c < 6; c++) a[c] = (float)(d_chsum[c] / 6400000.0);
    float t[30];
    for (int j = 0; j < 30; j++) {
        float s = fc1b[j];
        for (int c = 0; c < 6; c++) s += fc1w[j * 6 + c] * a[c];
        t[j] = fmaxf(s, 0.f);
    }
    for (int c = 0; c < 6; c++) {
        float s = fc2b[c];
        for (int j = 0; j < 30; j++) s += fc2w[c * 30 + j] * t[j];
        float sg = 1.f / (1.f + expf(-s));
        d_catt[c] = convw[c] * sg;
    }
    d_catt[6] = convb[0];
}

// ---------------- final combine ----------------
// out[n,d] = cb + sum_c catt[c] * XM_flat[(c*64+d)*N + n]
// block = 64 consecutive n, all 64 d; smem transpose for coalesced writes
__global__ void combine_kernel(float* __restrict__ out) {
    __shared__ float s[64][65];
    __shared__ float sc[8];
    int tid = threadIdx.x;
    if (tid < 8) sc[tid] = d_catt[tid];
    __syncthreads();
    int n0 = blockIdx.x * 64;
    int nl = tid & 63;
    int dg = tid >> 6;   // 0..3
    bool valid_n = (n0 + nl) < NN;
    float accs[16];
    #pragma unroll
    for (int i = 0; i < 16; i++) accs[i] = sc[6];
    for (int c = 0; c < 6; c++) {
        float a = sc[c];
        #pragma unroll
        for (int i = 0; i < 16; i++) {
            int dcol = i * 4 + dg;
            int idx = (c * 64 + dcol) * NN + n0 + nl;
            float v = valid_n ? d_XM[idx] : 0.f;
            accs[i] = fmaf(a, v, accs[i]);
        }
    }
    #pragma unroll
    for (int i = 0; i < 16; i++) { int dcol = i * 4 + dg; s[nl][dcol] = accs[i]; }
    __syncthreads();
    int dcol = tid & 63;
    int ng = tid >> 6;
    #pragma unroll
    for (int i = 0; i < 16; i++) {
        int nl2 = i * 4 + ng;
        int n = n0 + nl2;
        if (n < NN) out[(size_t)n * 64 + dcol] = s[nl2][dcol];
    }
}

// ---------------- launch ----------------
extern "C" void kernel_launch(void* const* d_in, const int* in_sizes, int n_in,
                              void* d_out, int out_size) {
    // Map inputs by element count (robust to either metadata ordering).
    const float *x = nullptr, *w[3] = {nullptr, nullptr, nullptr};
    const float *W1 = nullptr, *b1 = nullptr, *W2 = nullptr, *b2 = nullptr;
    const float *fc1w = nullptr, *fc1b = nullptr, *fc2w = nullptr, *fc2b = nullptr;
    const float *convw = nullptr, *convb = nullptr;
    const int* edges[3] = {nullptr, nullptr, nullptr};
    int nBig = 0, nW3 = 0, nWm = 0, nB = 0, nFc = 0, nSix = 0;
    for (int i = 0; i < n_in; i++) {
        int s = in_sizes[i];
        if (s == NN * DD) {                 // 6,400,000: x first, then edges g,c,f
            if (nBig == 0) x = (const float*)d_in[i];
            else if (nBig <= 3) edges[nBig - 1] = (const int*)d_in[i];
            nBig++;
        } else if (s == EE) {               // 3,200,000: w_g, w_c, w_f
            if (nW3 < 3) w[nW3] = (const float*)d_in[i];
            nW3++;
        } else if (s == 4096) {             // W1 then W2
            if (nWm == 0) W1 = (const float*)d_in[i]; else W2 = (const float*)d_in[i];
            nWm++;
        } else if (s == 64) {               // b1 then b2
            if (nB == 0) b1 = (const float*)d_in[i]; else b2 = (const float*)d_in[i];
            nB++;
        } else if (s == 180) {              // fc1_w then fc2_w
            if (nFc == 0) fc1w = (const float*)d_in[i]; else fc2w = (const float*)d_in[i];
            nFc++;
        } else if (s == 30) {
            fc1b = (const float*)d_in[i];
        } else if (s == 6) {                // fc2_b then conv_w
            if (nSix == 0) fc2b = (const float*)d_in[i]; else convw = (const float*)d_in[i];
            nSix++;
        } else if (s == 1) {
            convb = (const float*)d_in[i];
        }
    }

    const int TB = 256;
    const int gridE = (EE + TB - 1) / TB;        // 12500
    const int gridN8 = (NN * 32 + TB - 1) / TB;  // 12500 (warp per node)
    const int gridNz = (NN + TB - 1) / TB;       // 391
    const int gridG = (NN + 31) / 32;            // 3125
    const int gridC = (NN + 63) / 64;            // 1563

    // h1 = x @ W1 (shared by all three graphs)
    gemm_kernel<<<gridG, TB>>>(x, 64, 0, W1, 0);

    for (int g = 0; g < 3; g++) {
        const int* rows = edges[g];
        const int* cols = edges[g] + EE;
        // CSR build (counting sort by destination)
        zero_cnt_kernel<<<gridNz, TB>>>();
        count_kernel<<<gridE, TB>>>(cols);
        scan_kernel<<<1, 1024>>>();
        scatter_kernel<<<gridE, TB>>>(rows, cols, w[g]);
        dinv_kernel<<<gridN8, TB>>>();
        norm_kernel<<<gridN8, TB>>>();
        // layer 1: aggregate h1 -> XM block 2g
        agg_kernel<<<gridN8, TB>>>(0, b1, 2 * g);
        // layer 2: h2 = block(2g) @ W2 ; aggregate -> XM block 2g+1
        gemm_kernel<<<gridG, TB>>>(nullptr, 384, 2 * g * 64, W2, 1);
        agg_kernel<<<gridN8, TB>>>(1, b2, 2 * g + 1);
    }

    // SE attention + final combine
    zero_chsum_kernel<<<1, 32>>>();
    chsum_kernel<<<6 * 128, TB>>>();
    att_kernel<<<1, 32>>>(fc1w, fc1b, fc2w, fc2b, convw, convb);
    combine_kernel<<<gridC, TB>>>((float*)d_out);
}

// round 3
// speedup vs baseline: 1.0023x; 1.0023x over previous
#include <cuda_runtime.h>
#include <math.h>

#define NN 100000
#define EE 3200000
#define DD 64

// ---------------- device scratch (static, allowed) ----------------
__device__ float  d_h1[NN * DD];            // x @ W1 (shared by all 3 graphs)
__device__ float  d_h2[NN * DD];            // layer-2 gemm output
__device__ float  d_XM[(size_t)NN * 384];   // [N, 6*64] concat, row-major
__device__ int    d_csr_row[EE];
__device__ float  d_csr_w[EE];              // ew_sorted, overwritten in-place by norm
__device__ int    d_off[NN + 1];
__device__ int    d_cursor[NN];
__device__ int    d_cnt[NN];
__device__ float  d_dinv[NN];
__device__ double d_chsum[6];
__device__ float  d_catt[8];                // [0..5]=conv_w*att, [6]=conv_b

// ---------------- small utility kernels ----------------
__global__ void zero_cnt_kernel() {
    int i = blockIdx.x * blockDim.x + threadIdx.x;
    if (i < NN) d_cnt[i] = 0;
}

__global__ void zero_chsum_kernel() {
    if (threadIdx.x < 6) d_chsum[threadIdx.x] = 0.0;
}

// ---------------- CSR build ----------------
__global__ void count_kernel(const int* __restrict__ col) {
    int e = blockIdx.x * blockDim.x + threadIdx.x;
    if (e < EE) atomicAdd(&d_cnt[col[e]], 1);
}

// single-block exclusive scan of d_cnt[0..NN) -> d_off, d_cursor; d_off[NN]=E
__global__ void scan_kernel() {
    __shared__ int s[1024];
    int t = threadIdx.x;
    const int C = (NN + 1023) / 1024;   // 98
    int beg = t * C;
    int end = beg + C; if (end > NN) end = NN;
    int sum = 0;
    for (int i = beg; i < end; i++) sum += d_cnt[i];
    s[t] = sum;
    __syncthreads();
    // Hillis-Steele inclusive scan over 1024 partials
    for (int st = 1; st < 1024; st <<= 1) {
        int v = (t >= st) ? s[t - st] : 0;
        __syncthreads();
        s[t] += v;
        __syncthreads();
    }
    int run = (t == 0) ? 0 : s[t - 1];
    for (int i = beg; i < end; i++) {
        d_off[i] = run;
        d_cursor[i] = run;
        run += d_cnt[i];
    }
    if (t == 1023) d_off[NN] = s[1023];
}

__global__ void scatter_kernel(const int* __restrict__ row,
                               const int* __restrict__ col,
                               const float* __restrict__ ew) {
    int e = blockIdx.x * blockDim.x + threadIdx.x;
    if (e < EE) {
        int c = col[e];
        int p = atomicAdd(&d_cursor[c], 1);
        d_csr_row[p] = row[e];
        d_csr_w[p]   = ew[e];
    }
}

// warp per node: deg = 1 + sum(ew over incoming slice); dinv = rsqrt(deg)
__global__ void dinv_kernel() {
    int v = (blockIdx.x * blockDim.x + threadIdx.x) >> 5;
    int lane = threadIdx.x & 31;
    if (v >= NN) return;
    int b = d_off[v], e = d_off[v + 1];
    float s = 0.f;
    for (int p = b + lane; p < e; p += 32) s += d_csr_w[p];
    #pragma unroll
    for (int o = 16; o; o >>= 1) s += __shfl_xor_sync(0xffffffffu, s, o);
    if (lane == 0) d_dinv[v] = rsqrtf(1.0f + s);
}

// warp per node: ew -> norm = dinv[row]*ew*dinv[v]  (in place)
__global__ void norm_kernel() {
    int v = (blockIdx.x * blockDim.x + threadIdx.x) >> 5;
    int lane = threadIdx.x & 31;
    if (v >= NN) return;
    float dv = d_dinv[v];
    int b = d_off[v], e = d_off[v + 1];
    for (int p = b + lane; p < e; p += 32)
        d_csr_w[p] = d_dinv[d_csr_row[p]] * d_csr_w[p] * dv;
}

// ---------------- dense 64x64 GEMM over 100k rows ----------------
// out[r][d] = sum_k in[r*istride+k] * W[k*64+d]    (no bias here)
// in_ext == nullptr -> read from d_XM + xoff (stride istride)
// out_sel: 0 -> d_h1, 1 -> d_h2
__global__ void gemm_kernel(const float* __restrict__ in_ext, int istride, int xoff,
                            const float* __restrict__ W, int out_sel) {
    __shared__ float sW[64 * 64];
    __shared__ float sI[32 * 64];
    const float* in = in_ext ? in_ext : (d_XM + xoff);
    float* out = out_sel ? d_h2 : d_h1;
    int tid = threadIdx.x;
    for (int i = tid; i < 4096; i += 256) sW[i] = W[i];
    int row0 = blockIdx.x * 32;
    for (int i = tid; i < 2048; i += 256) {
        int r = i >> 6, k = i & 63;
        int rr = row0 + r;
        sI[i] = (rr < NN) ? in[(size_t)rr * istride + k] : 0.f;
    }
    __syncthreads();
    int dcol = tid & 63, rs = tid >> 6;
    for (int r = rs; r < 32; r += 4) {
        float acc = 0.f;
        #pragma unroll
        for (int k = 0; k < 64; k++) acc = fmaf(sI[r * 64 + k], sW[k * 64 + dcol], acc);
        int rr = row0 + r;
        if (rr < NN) out[(size_t)rr * 64 + dcol] = acc;
    }
}

// ---------------- aggregation: warp per node, float2 per lane ----------------
// out_v = relu( sum_p norm[p]*h[row[p]] + dinv[v]^2*h[v] + bias )
// written into d_XM at column block blk (64 floats = 32 float2)
__global__ void agg_kernel(int h_sel, const float* __restrict__ bias, int blk) {
    int v = (blockIdx.x * blockDim.x + threadIdx.x) >> 5;
    int lane = threadIdx.x & 31;
    if (v >= NN) return;
    const float2* h2 = (const float2*)(h_sel ? d_h2 : d_h1);
    float2 acc = make_float2(0.f, 0.f);
    int b = d_off[v], e = d_off[v + 1];
    for (int p = b; p < e; p++) {
        int r = __ldg(&d_csr_row[p]);
        float w = __ldg(&d_csr_w[p]);
        float2 hv = h2[(size_t)r * 32 + lane];
        acc.x = fmaf(w, hv.x, acc.x);
        acc.y = fmaf(w, hv.y, acc.y);
    }
    float dv = d_dinv[v];
    float dv2 = dv * dv;
    float2 hs = h2[(size_t)v * 32 + lane];
    acc.x = fmaf(dv2, hs.x, acc.x);
    acc.y = fmaf(dv2, hs.y, acc.y);
    float2 bb = ((const float2*)bias)[lane];
    acc.x = fmaxf(acc.x + bb.x, 0.f);
    acc.y = fmaxf(acc.y + bb.y, 0.f);
    ((float2*)d_XM)[(size_t)v * 192 + blk * 32 + lane] = acc;
}

// ---------------- channel sums for SE attention ----------------
// att_in[c] = mean of XM_flat[c*6400000 .. (c+1)*6400000)
__global__ void chsum_kernel() {
    int ch = blockIdx.x >> 7;       // 128 blocks per channel
    int bl = blockIdx.x & 127;
    size_t base = (size_t)ch * 6400000;
    float s = 0.f;
    for (size_t i = (size_t)bl * 256 + threadIdx.x; i < 6400000; i += 128 * 256)
        s += d_XM[base + i];
    #pragma unroll
    for (int o = 16; o; o >>= 1) s += __shfl_xor_sync(0xffffffffu, s, o);
    __shared__ float ws[8];
    int lane = threadIdx.x & 31, w = threadIdx.x >> 5;
    if (lane == 0) ws[w] = s;
    __syncthreads();
    if (threadIdx.x < 8) {
        float t = ws[threadIdx.x];
        #pragma unroll
        for (int o = 4; o; o >>= 1) t += __shfl_xor_sync(0xffu, t, o, 8);
        if (threadIdx.x == 0) atomicAdd(&d_chsum[ch], (double)t);
    }
}

// ---------------- tiny SE MLP: fc1(relu) -> fc2(sigmoid) -> * conv_w ----------------
__global__ void att_kernel(const float* __restrict__ fc1w, const float* __restrict__ fc1b,
                           const float* __restrict__ fc2w, const float* __restrict__ fc2b,
                           const float* __restrict__ convw, const float* __restrict__ convb) {
    if (threadIdx.x != 0 || blockIdx.x != 0) return;
    float a[6];
    for (int c = 0; c < 6; c++) a[c] = (float)(d_chsum[c] / 6400000.0);
    float t[30];
    for (int j = 0; j < 30; j++) {
        float s = fc1b[j];
        for (int c = 0; c < 6; c++) s += fc1w[j * 6 + c] * a[c];
        t[j] = fmaxf(s, 0.f);
    }
    for (int c = 0; c < 6; c++) {
        float s = fc2b[c];
        for (int j = 0; j < 30; j++) s += fc2w[c * 30 + j] * t[j];
        float sg = 1.f / (1.f + expf(-s));
        d_catt[c] = convw[c] * sg;
    }
    d_catt[6] = convb[0];
}

// ---------------- final combine ----------------
// out[n,d] = cb + sum_c catt[c] * XM_flat[(c*64+d)*N + n]
// block = 64 consecutive n, all 64 d; smem transpose for coalesced writes
__global__ void combine_kernel(float* __restrict__ out) {
    __shared__ float s[64][65];
    __shared__ float sc[8];
    int tid = threadIdx.x;
    if (tid < 8) sc[tid] = d_catt[tid];
    __syncthreads();
    int n0 = blockIdx.x * 64;
    int nl = tid & 63;
    int dg = tid >> 6;   // 0..3
    bool valid_n = (n0 + nl) < NN;
    float accs[16];
    #pragma unroll
    for (int i = 0; i < 16; i++) accs[i] = sc[6];
    for (int c = 0; c < 6; c++) {
        float a = sc[c];
        #pragma unroll
        for (int i = 0; i < 16; i++) {
            int dcol = i * 4 + dg;
            int idx = (c * 64 + dcol) * NN + n0 + nl;
            float v = valid_n ? d_XM[idx] : 0.f;
            accs[i] = fmaf(a, v, accs[i]);
        }
    }
    #pragma unroll
    for (int i = 0; i < 16; i++) { int dcol = i * 4 + dg; s[nl][dcol] = accs[i]; }
    __syncthreads();
    int dcol = tid & 63;
    int ng = tid >> 6;
    #pragma unroll
    for (int i = 0; i < 16; i++) {
        int nl2 = i * 4 + ng;
        int n = n0 + nl2;
        if (n < NN) out[(size_t)n * 64 + dcol] = s[nl2][dcol];
    }
}

// ---------------- launch ----------------
extern "C" void kernel_launch(void* const* d_in, const int* in_sizes, int n_in,
                              void* d_out, int out_size) {
    // Map inputs by element count (robust to either metadata ordering).
    const float *x = nullptr, *w[3] = {nullptr, nullptr, nullptr};
    const float *W1 = nullptr, *b1 = nullptr, *W2 = nullptr, *b2 = nullptr;
    const float *fc1w = nullptr, *fc1b = nullptr, *fc2w = nullptr, *fc2b = nullptr;
    const float *convw = nullptr, *convb = nullptr;
    const int* edges[3] = {nullptr, nullptr, nullptr};
    int nBig = 0, nW3 = 0, nWm = 0, nB = 0, nFc = 0, nSix = 0;
    for (int i = 0; i < n_in; i++) {
        int s = in_sizes[i];
        if (s == NN * DD) {                 // 6,400,000: x first, then edges g,c,f
            if (nBig == 0) x = (const float*)d_in[i];
            else if (nBig <= 3) edges[nBig - 1] = (const int*)d_in[i];
            nBig++;
        } else if (s == EE) {               // 3,200,000: w_g, w_c, w_f
            if (nW3 < 3) w[nW3] = (const float*)d_in[i];
            nW3++;
        } else if (s == 4096) {             // W1 then W2
            if (nWm == 0) W1 = (const float*)d_in[i]; else W2 = (const float*)d_in[i];
            nWm++;
        } else if (s == 64) {               // b1 then b2
            if (nB == 0) b1 = (const float*)d_in[i]; else b2 = (const float*)d_in[i];
            nB++;
        } else if (s == 180) {              // fc1_w then fc2_w
            if (nFc == 0) fc1w = (const float*)d_in[i]; else fc2w = (const float*)d_in[i];
            nFc++;
        } else if (s == 30) {
            fc1b = (const float*)d_in[i];
        } else if (s == 6) {                // fc2_b then conv_w
            if (nSix == 0) fc2b = (const float*)d_in[i]; else convw = (const float*)d_in[i];
            nSix++;
        } else if (s == 1) {
            convb = (const float*)d_in[i];
        }
    }

    const int TB = 256;
    const int gridE = (EE + TB - 1) / TB;        // 12500
    const int gridN8 = (NN * 32 + TB - 1) / TB;  // 12500 (warp per node)
    const int gridNz = (NN + TB - 1) / TB;       // 391
    const int gridG = (NN + 31) / 32;            // 3125
    const int gridC = (NN + 63) / 64;            // 1563

    // h1 = x @ W1 (shared by all three graphs)
    gemm_kernel<<<gridG, TB>>>(x, 64, 0, W1, 0);

    for (int g = 0; g < 3; g++) {
        const int* rows = edges[g];
        const int* cols = edges[g] + EE;
        // CSR build (counting sort by destination)
        zero_cnt_kernel<<<gridNz, TB>>>();
        count_kernel<<<gridE, TB>>>(cols);
        scan_kernel<<<1, 1024>>>();
        scatter_kernel<<<gridE, TB>>>(rows, cols, w[g]);
        dinv_kernel<<<gridN8, TB>>>();
        norm_kernel<<<gridN8, TB>>>();
        // layer 1: aggregate h1 -> XM block 2g
        agg_kernel<<<gridN8, TB>>>(0, b1, 2 * g);
        // layer 2: h2 = block(2g) @ W2 ; aggregate -> XM block 2g+1
        gemm_kernel<<<gridG, TB>>>(nullptr, 384, 2 * g * 64, W2, 1);
        agg_kernel<<<gridN8, TB>>>(1, b2, 2 * g + 1);
    }

    // SE attention + final combine
    zero_chsum_kernel<<<1, 32>>>();
    chsum_kernel<<<6 * 128, TB>>>();
    att_kernel<<<1, 32>>>(fc1w, fc1b, fc2w, fc2b, convw, convb);
    combine_kernel<<<gridC, TB>>>((float*)d_out);
}